// round 1
// baseline (speedup 1.0000x reference)
#include <cuda_runtime.h>
#include <math.h>

// Problem constants
#define NNODE 2048
#define NEDGE 4096
#define LF    49          // full L
#define LR    16          // reduced
#define MMID  25
#define NYR   3
#define CCH   128
#define HID   128
#define XLC   (LF*CCH)    // 6272
#define T_W   1225        // 49*25 / 25*49 flattened
#define FEATW 2064        // 16*129
#define MSGW  2048        // 16*128

__device__ float g_xe  [NEDGE*HID];
__device__ float g_xm  [NEDGE*LF];
__device__ float g_ym  [NEDGE*LF];
__device__ float g_t   [NEDGE*T_W];
__device__ float g_mid [NEDGE*MMID];
__device__ float g_A   [NEDGE*LF];
__device__ float g_feat[NEDGE*FEATW];
__device__ float g_h   [NEDGE*HID];
__device__ float g_h2  [NEDGE*MSGW];
__device__ float g_sh  [NEDGE*LR*CCH];
__device__ float g_msg [NEDGE*NYR*MSGW];
__device__ float g_m1  [NEDGE*NYR*HID];
__device__ float g_m2  [NEDGE*NYR*MSGW];

__device__ __forceinline__ float silu_f(float v) {
    return v / (1.0f + __expf(-v));
}

// ---------------------------------------------------------------------------
// Generic tiled SGEMM: C[M,N] = A[M,K] * B[K,N], row-major.
// EPI: 0 = plain, 1 = bias+silu, 2 = bias+silu then *= xe[(row/3)*128+col]
// ---------------------------------------------------------------------------
template<int EPI>
__global__ __launch_bounds__(256)
void sgemm_k(const float* __restrict__ A, const float* __restrict__ B,
             const float* __restrict__ bias, const float* __restrict__ xe,
             float* __restrict__ C, int M, int N, int K)
{
    __shared__ float As[16][68];   // padded for float4 + conflict avoidance
    __shared__ float Bs[16][64];

    int tid = threadIdx.x;
    int bm0 = blockIdx.y * 64;
    int bn0 = blockIdx.x * 64;
    int ty = tid >> 4, tx = tid & 15;

    float acc[4][4];
#pragma unroll
    for (int i = 0; i < 4; i++)
#pragma unroll
        for (int j = 0; j < 4; j++) acc[i][j] = 0.0f;

    int nk = (K + 15) >> 4;
    for (int t = 0; t < nk; t++) {
        int k0 = t << 4;
#pragma unroll
        for (int i = 0; i < 4; i++) {
            int idx = tid + i * 256;
            int r = idx >> 4, kk = idx & 15;
            int gr = bm0 + r, gk = k0 + kk;
            As[kk][r] = (gr < M && gk < K) ? A[gr * K + gk] : 0.0f;
        }
#pragma unroll
        for (int i = 0; i < 4; i++) {
            int idx = tid + i * 256;
            int kr = idx >> 6, c = idx & 63;
            int gk = k0 + kr, gc = bn0 + c;
            Bs[kr][c] = (gk < K && gc < N) ? B[gk * N + gc] : 0.0f;
        }
        __syncthreads();
#pragma unroll
        for (int kk = 0; kk < 16; kk++) {
            float4 av = *(const float4*)&As[kk][ty * 4];
            float4 bv = *(const float4*)&Bs[kk][tx * 4];
            float a0 = av.x, a1 = av.y, a2 = av.z, a3 = av.w;
            float b0 = bv.x, b1 = bv.y, b2 = bv.z, b3 = bv.w;
            acc[0][0] = fmaf(a0, b0, acc[0][0]); acc[0][1] = fmaf(a0, b1, acc[0][1]);
            acc[0][2] = fmaf(a0, b2, acc[0][2]); acc[0][3] = fmaf(a0, b3, acc[0][3]);
            acc[1][0] = fmaf(a1, b0, acc[1][0]); acc[1][1] = fmaf(a1, b1, acc[1][1]);
            acc[1][2] = fmaf(a1, b2, acc[1][2]); acc[1][3] = fmaf(a1, b3, acc[1][3]);
            acc[2][0] = fmaf(a2, b0, acc[2][0]); acc[2][1] = fmaf(a2, b1, acc[2][1]);
            acc[2][2] = fmaf(a2, b2, acc[2][2]); acc[2][3] = fmaf(a2, b3, acc[2][3]);
            acc[3][0] = fmaf(a3, b0, acc[3][0]); acc[3][1] = fmaf(a3, b1, acc[3][1]);
            acc[3][2] = fmaf(a3, b2, acc[3][2]); acc[3][3] = fmaf(a3, b3, acc[3][3]);
        }
        __syncthreads();
    }

#pragma unroll
    for (int i = 0; i < 4; i++) {
        int row = bm0 + ty * 4 + i;
        if (row >= M) continue;
#pragma unroll
        for (int j = 0; j < 4; j++) {
            int col = bn0 + tx * 4 + j;
            if (col >= N) continue;
            float v = acc[i][j];
            if (EPI >= 1) { v += bias[col]; v = silu_f(v); }
            if (EPI == 2) { v *= xe[(row / 3) * 128 + col]; }
            C[row * N + col] = v;
        }
    }
}

// ---------------------------------------------------------------------------
// xm[e,l] = mean_c x[src,l,c]; ym[e,l] = mean_c x[dst,l,c]
// ---------------------------------------------------------------------------
__global__ void k_xmym(const float* __restrict__ x, const int* __restrict__ eidx,
                       float* __restrict__ xm, float* __restrict__ ym)
{
    int e = blockIdx.x, tid = threadIdx.x;
    int lane = tid & 31, warp = tid >> 5;
    int src = eidx[e], dst = eidx[NEDGE + e];
    const float* ps = x + src * XLC;
    const float* pt = x + dst * XLC;
    for (int l = warp; l < LF; l += 4) {
        const float* a = ps + l * 128;
        const float* b = pt + l * 128;
        float s = a[lane] + a[lane + 32] + a[lane + 64] + a[lane + 96];
        float u = b[lane] + b[lane + 32] + b[lane + 64] + b[lane + 96];
#pragma unroll
        for (int o = 16; o > 0; o >>= 1) {
            s += __shfl_xor_sync(0xffffffffu, s, o);
            u += __shfl_xor_sync(0xffffffffu, u, o);
        }
        if (lane == 0) {
            xm[e * LF + l] = s * (1.0f / 128.0f);
            ym[e * LF + l] = u * (1.0f / 128.0f);
        }
    }
}

// mid[e,o] = sum_j ym[e,j] * t[e, j*25 + o]   (o<25, j<49)
__global__ void k_mid(const float* __restrict__ ym, const float* __restrict__ t,
                      float* __restrict__ mid)
{
    int e = blockIdx.x, tid = threadIdx.x;
    __shared__ float ys[LF];
    if (tid < LF) ys[tid] = ym[e * LF + tid];
    __syncthreads();
    if (tid < MMID) {
        const float* tp = t + e * T_W + tid;
        float s = 0.0f;
#pragma unroll
        for (int j = 0; j < LF; j++) s = fmaf(ys[j], tp[j * MMID], s);
        mid[e * MMID + tid] = s;
    }
}

// A[e,o] (+)= sum_j mid[e,j] * t[e, j*49 + o]   (o<49, j<25)
template<int ACC>
__global__ void k_contract(const float* __restrict__ mid, const float* __restrict__ t,
                           float* __restrict__ Aout)
{
    int e = blockIdx.x, tid = threadIdx.x;
    __shared__ float ms[MMID];
    if (tid < MMID) ms[tid] = mid[e * MMID + tid];
    __syncthreads();
    if (tid < LF) {
        const float* tp = t + e * T_W + tid;
        float s = ACC ? Aout[e * LF + tid] : 0.0f;
#pragma unroll
        for (int j = 0; j < MMID; j++) s = fmaf(ms[j], tp[j * LF], s);
        Aout[e * LF + tid] = s;
    }
}

// ---------------------------------------------------------------------------
// node_interaction front: ne = wig_node^T @ x[node][:16], feat = [ne | mean*g]
// feat[e, i*129 + c] = ne[i,c];  feat[e, i*129+128] = mean_c(ne[i]) * g[other,i]
// ---------------------------------------------------------------------------
__global__ void k_feat(const float* __restrict__ x, const float* __restrict__ glovec,
                       const float* __restrict__ wign, const int* __restrict__ eidx,
                       int node_off, int other_off, float* __restrict__ feat)
{
    int e = blockIdx.x, tid = threadIdx.x;   // 128 threads = channel c
    __shared__ float wigS[256];
    __shared__ float gS[16];
    __shared__ float red[4];
    int node  = eidx[node_off  + e];
    int other = eidx[other_off + e];
    wigS[tid]       = wign[e * 256 + tid];
    wigS[tid + 128] = wign[e * 256 + 128 + tid];
    if (tid < 16) gS[tid] = glovec[other * LR + tid];
    __syncthreads();

    float xr[16];
    const float* xp = x + node * XLC;
#pragma unroll
    for (int j = 0; j < 16; j++) xr[j] = xp[j * 128 + tid];

    float* fp = feat + e * FEATW;
    for (int i = 0; i < 16; i++) {
        float a = 0.0f;
#pragma unroll
        for (int j = 0; j < 16; j++) a = fmaf(wigS[j * 16 + i], xr[j], a);
        fp[i * 129 + tid] = a;
        float s = a;
#pragma unroll
        for (int o = 16; o > 0; o >>= 1) s += __shfl_xor_sync(0xffffffffu, s, o);
        if ((tid & 31) == 0) red[tid >> 5] = s;
        __syncthreads();
        if (tid == 0)
            fp[i * 129 + 128] = (red[0] + red[1] + red[2] + red[3]) * (1.0f / 128.0f) * gS[i];
        __syncthreads();
    }
}

// sh[e,i,c] (+)= sum_j wig_node[e,i,j] * h2[e, j*128 + c]
template<int ACC>
__global__ void k_sh(const float* __restrict__ wign, const float* __restrict__ h2,
                     float* __restrict__ sh)
{
    int e = blockIdx.x, tid = threadIdx.x;   // 128 threads
    __shared__ float wigS[256];
    wigS[tid]       = wign[e * 256 + tid];
    wigS[tid + 128] = wign[e * 256 + 128 + tid];
    __syncthreads();
    float hr[16];
    const float* hp = h2 + e * MSGW;
#pragma unroll
    for (int j = 0; j < 16; j++) hr[j] = hp[j * 128 + tid];
    float* sp = sh + e * MSGW;
#pragma unroll
    for (int i = 0; i < 16; i++) {
        float s = 0.0f;
#pragma unroll
        for (int j = 0; j < 16; j++) s = fmaf(wigS[i * 16 + j], hr[j], s);
        if (ACC) sp[i * 128 + tid] += s; else sp[i * 128 + tid] = s;
    }
}

// ---------------------------------------------------------------------------
// z[l,c] = 2*(xs+xt) + A[l] + (l<16 ? sh[l,c] : 0)
// msg[e, n*16+r, c] = sum_l wigner[e,(n,r),l] * z[l,c]
// ---------------------------------------------------------------------------
__global__ __launch_bounds__(256)
void k_rotmsg(const float* __restrict__ x, const int* __restrict__ eidx,
              const float* __restrict__ Aarr, const float* __restrict__ sh,
              const float* __restrict__ wigner, float* __restrict__ msg)
{
    int e = blockIdx.x, tid = threadIdx.x;
    __shared__ float zs[LF * 128];      // 25 KB
    __shared__ float wgS[48 * 49];      // 9.2 KB
    int src = eidx[e], dst = eidx[NEDGE + e];
    const float* xs = x + src * XLC;
    const float* xt = x + dst * XLC;
    const float* shp = sh + e * MSGW;
    const float* Ap  = Aarr + e * LF;
    for (int idx = tid; idx < LF * 128; idx += 256) {
        int l = idx >> 7, c = idx & 127;
        float v = 2.0f * (xs[idx] + xt[idx]) + Ap[l];
        if (l < 16) v += shp[l * 128 + c];
        zs[idx] = v;
    }
    const float* wp = wigner + e * (48 * 49);
    for (int idx = tid; idx < 48 * 49; idx += 256) wgS[idx] = wp[idx];
    __syncthreads();

    int cg = tid & 63, grp = tid >> 6;      // grp handles 12 rows, cg -> 2 channels
    float2 acc[12];
#pragma unroll
    for (int rr = 0; rr < 12; rr++) { acc[rr].x = 0.0f; acc[rr].y = 0.0f; }
    const float2* z2 = (const float2*)zs;
    for (int l = 0; l < LF; l++) {
        float2 zv = z2[l * 64 + cg];
#pragma unroll
        for (int rr = 0; rr < 12; rr++) {
            float w = wgS[(grp * 12 + rr) * LF + l];
            acc[rr].x = fmaf(w, zv.x, acc[rr].x);
            acc[rr].y = fmaf(w, zv.y, acc[rr].y);
        }
    }
    float* mp = msg + e * (NYR * MSGW);
#pragma unroll
    for (int rr = 0; rr < 12; rr++) {
        int row = grp * 12 + rr;
        ((float2*)(mp + row * 128))[cg] = acc[rr];
    }
}

// ---------------------------------------------------------------------------
// mm[r,c] = mean_n m2[e*3+n, r*128+c]; out[e,b,c] = invsqrt3 * sum_r winv[b,r]*mm[r,c]
// ---------------------------------------------------------------------------
__global__ __launch_bounds__(256)
void k_out(const float* __restrict__ m2, const float* __restrict__ winv,
           float* __restrict__ out)
{
    int e = blockIdx.x, tid = threadIdx.x;
    __shared__ float mmS[16 * 128];
    __shared__ float wvS[LF * 16];
    const float* mp = m2 + e * (NYR * MSGW);
    for (int idx = tid; idx < 2048; idx += 256)
        mmS[idx] = (mp[idx] + mp[idx + 2048] + mp[idx + 4096]) * (1.0f / 3.0f);
    const float* wp = winv + e * (LF * 16);
    for (int idx = tid; idx < LF * 16; idx += 256) wvS[idx] = wp[idx];
    __syncthreads();

    const float INV3 = 0.5773502691896258f;
    int cg = tid & 63, grp = tid >> 6;
    const float2* mm2 = (const float2*)mmS;
    float* op = out + e * XLC;
    for (int b = grp; b < LF; b += 4) {
        float2 s; s.x = 0.0f; s.y = 0.0f;
#pragma unroll
        for (int r = 0; r < 16; r++) {
            float w = wvS[b * 16 + r];
            float2 mv = mm2[r * 64 + cg];
            s.x = fmaf(w, mv.x, s.x);
            s.y = fmaf(w, mv.y, s.y);
        }
        s.x *= INV3; s.y *= INV3;
        ((float2*)(op + b * 128))[cg] = s;
    }
}

// ---------------------------------------------------------------------------
extern "C" void kernel_launch(void* const* d_in, const int* in_sizes, int n_in,
                              void* d_out, int out_size)
{
    const float* x      = (const float*)d_in[0];
    const float* glovec = (const float*)d_in[2];
    const float* x_edge = (const float*)d_in[3];
    const int*   eidx   = (const int*)  d_in[4];
    const float* W_cg1  = (const float*)d_in[8];
    const float* W_cg21 = (const float*)d_in[9];
    const float* W_cg22 = (const float*)d_in[10];
    const float* Wn1a   = (const float*)d_in[11];
    const float* bn1a   = (const float*)d_in[12];
    const float* Wn1b   = (const float*)d_in[13];
    const float* bn1b   = (const float*)d_in[14];
    const float* Wn2a   = (const float*)d_in[15];
    const float* bn2a   = (const float*)d_in[16];
    const float* Wn2b   = (const float*)d_in[17];
    const float* bn2b   = (const float*)d_in[18];
    const float* Wd     = (const float*)d_in[19];
    const float* bd     = (const float*)d_in[20];
    const float* Wp1    = (const float*)d_in[21];
    const float* bp1    = (const float*)d_in[22];
    const float* Wp2    = (const float*)d_in[23];
    const float* bp2    = (const float*)d_in[24];
    const float* wigner = (const float*)d_in[25];
    const float* winv   = (const float*)d_in[26];
    const float* wign   = (const float*)d_in[27];
    float* out = (float*)d_out;

    float *p_xe, *p_xm, *p_ym, *p_t, *p_mid, *p_A, *p_feat, *p_h, *p_h2,
          *p_sh, *p_msg, *p_m1, *p_m2;
    cudaGetSymbolAddress((void**)&p_xe,   g_xe);
    cudaGetSymbolAddress((void**)&p_xm,   g_xm);
    cudaGetSymbolAddress((void**)&p_ym,   g_ym);
    cudaGetSymbolAddress((void**)&p_t,    g_t);
    cudaGetSymbolAddress((void**)&p_mid,  g_mid);
    cudaGetSymbolAddress((void**)&p_A,    g_A);
    cudaGetSymbolAddress((void**)&p_feat, g_feat);
    cudaGetSymbolAddress((void**)&p_h,    g_h);
    cudaGetSymbolAddress((void**)&p_h2,   g_h2);
    cudaGetSymbolAddress((void**)&p_sh,   g_sh);
    cudaGetSymbolAddress((void**)&p_msg,  g_msg);
    cudaGetSymbolAddress((void**)&p_m1,   g_m1);
    cudaGetSymbolAddress((void**)&p_m2,   g_m2);

    auto grid = [](int M, int N) { return dim3((N + 63) / 64, (M + 63) / 64); };

    // 1. xe = silu(x_edge @ Wd + bd)
    sgemm_k<1><<<grid(NEDGE, HID), 256>>>(x_edge, Wd, bd, nullptr, p_xe, NEDGE, HID, 128);

    // 2. channel means of gathered features
    k_xmym<<<NEDGE, 128>>>(x, eidx, p_xm, p_ym);

    // 3. CG bilinears -> A[e,l]
    sgemm_k<0><<<grid(NEDGE, T_W), 256>>>(p_xm, W_cg1, nullptr, nullptr, p_t, NEDGE, T_W, LF);
    k_mid<<<NEDGE, 64>>>(p_ym, p_t, p_mid);
    sgemm_k<0><<<grid(NEDGE, T_W), 256>>>(p_xm, W_cg21, nullptr, nullptr, p_t, NEDGE, T_W, LF);
    k_contract<0><<<NEDGE, 64>>>(p_mid, p_t, p_A);
    sgemm_k<0><<<grid(NEDGE, T_W), 256>>>(p_ym, W_cg22, nullptr, nullptr, p_t, NEDGE, T_W, LF);
    k_contract<1><<<NEDGE, 64>>>(p_mid, p_t, p_A);

    // 4. node_interaction 1 (src features, dst glovec)
    k_feat<<<NEDGE, 128>>>(x, glovec, wign, eidx, 0, NEDGE, p_feat);
    sgemm_k<1><<<grid(NEDGE, HID), 256>>>(p_feat, Wn1a, bn1a, nullptr, p_h, NEDGE, HID, FEATW);
    sgemm_k<1><<<grid(NEDGE, MSGW), 256>>>(p_h, Wn1b, bn1b, nullptr, p_h2, NEDGE, MSGW, HID);
    k_sh<0><<<NEDGE, 128>>>(wign, p_h2, p_sh);

    // 5. node_interaction 2 (dst features, src glovec)
    k_feat<<<NEDGE, 128>>>(x, glovec, wign, eidx, NEDGE, 0, p_feat);
    sgemm_k<1><<<grid(NEDGE, HID), 256>>>(p_feat, Wn2a, bn2a, nullptr, p_h, NEDGE, HID, FEATW);
    sgemm_k<1><<<grid(NEDGE, MSGW), 256>>>(p_h, Wn2b, bn2b, nullptr, p_h2, NEDGE, MSGW, HID);
    k_sh<1><<<NEDGE, 128>>>(wign, p_h2, p_sh);

    // 6. fused z-build + rotate -> msg [E*NY, 2048]
    k_rotmsg<<<NEDGE, 256>>>(x, eidx, p_A, p_sh, wigner, p_msg);

    // 7. edge MLP with xe modulation
    sgemm_k<2><<<grid(NEDGE * NYR, HID), 256>>>(p_msg, Wp1, bp1, p_xe, p_m1,
                                                NEDGE * NYR, HID, MSGW);
    sgemm_k<1><<<grid(NEDGE * NYR, MSGW), 256>>>(p_m1, Wp2, bp2, nullptr, p_m2,
                                                 NEDGE * NYR, MSGW, HID);

    // 8. NY-mean + inverse rotation -> output [E,49,128]
    k_out<<<NEDGE, 256>>>(p_m2, winv, out);
}